// round 15
// baseline (speedup 1.0000x reference)
#include <cuda_runtime.h>
#include <cuda_bf16.h>
#include <cuda_fp16.h>
#include <mma.h>
#include <cstdint>

using namespace nvcuda;

#define N_NODES 50000
#define N_EDGES 800000
#define DIM 128
#define NCLS 16
#define BM 128
#define BK 32
#define N_PAD 50048            // 391 * 128, padded scratch rows
#define NBLK_SCAN 196          // ceil(50000/256)
#define NB_GEMM 391

// ---------------- scratch (allocation-free: __device__ globals) ----------------
__device__ __half g_h16[N_PAD * DIM];          // post-GEMM features, fp16 (SpMM gather)
__device__ __nv_bfloat16 g_xh[N_PAD * DIM];    // pre-split (x*iso) hi  (GEMM A input)
__device__ __nv_bfloat16 g_xl[N_PAD * DIM];    // pre-split (x*iso) lo
__device__ float g_x[N_PAD * DIM];             // final activations, fp32 (k_out input)
__device__ float g_res[N_PAD * DIM];           // residual branch, fp32
__device__ float g_iso[N_NODES];
__device__ float g_isi[N_NODES];
__device__ int   g_dego[N_NODES];
__device__ int   g_degi[N_NODES];
__device__ int   g_rowptr[N_NODES + 1];
__device__ int   g_cursor[N_NODES];
__device__ int   g_bsum[NBLK_SCAN];
__device__ int2  g_epack[N_EDGES];             // (src, weight bits)
__device__ __nv_bfloat16 g_wbh[5 * DIM * DIM]; // bf16 hi of weights, natural [k][n]
__device__ __nv_bfloat16 g_wbl[5 * DIM * DIM]; // bf16 lo residuals

// ---------------- cp.async helpers ----------------
__device__ __forceinline__ void cp16(uint32_t dst, const void* src) {
    asm volatile("cp.async.cg.shared.global [%0], [%1], 16;" :: "r"(dst), "l"(src));
}
#define CP_COMMIT() asm volatile("cp.async.commit_group;" ::: "memory")
#define CP_WAIT0()  asm volatile("cp.async.wait_group 0;" ::: "memory")

// ---------------- graph preprocessing ----------------
// fused: zero degrees + split all 5 weights into bf16 hi/lo
__global__ void k_init(const float* __restrict__ W1, const float* __restrict__ W2,
                       const float* __restrict__ W3, const float* __restrict__ W4,
                       const float* __restrict__ Wr) {
    const float* Ws[5] = {W1, W2, W3, W4, Wr};
    int i = blockIdx.x * 256 + threadIdx.x;      // 0..50175
    if (i < N_NODES) { g_dego[i] = 0; g_degi[i] = 0; }
    for (int j = i; j < 5 * DIM * DIM; j += NBLK_SCAN * 256) {
        int w = j >> 14;                          // /16384
        int k = j & (DIM * DIM - 1);
        float v = Ws[w][k];
        __nv_bfloat16 hi = __float2bfloat16(v);
        g_wbh[j] = hi;
        g_wbl[j] = __float2bfloat16(v - __bfloat162float(hi));
    }
}

__global__ void k_degrees(const int* __restrict__ src, const int* __restrict__ dst) {
    int e = blockIdx.x * blockDim.x + threadIdx.x;
    if (e < N_EDGES) {
        atomicAdd(&g_dego[src[e]], 1);
        atomicAdd(&g_degi[dst[e]], 1);
    }
}

// block-level scan of degi + invsqrt of both degrees (fused)
__global__ void k_scan_part() {
    __shared__ int ws[8];
    int t = threadIdx.x, lane = t & 31, w = t >> 5;
    int i = blockIdx.x * 256 + t;
    int v = (i < N_NODES) ? g_degi[i] : 0;
    if (i < N_NODES) {
        int dout = g_dego[i]; if (dout < 1) dout = 1;
        int din  = v;         if (din  < 1) din  = 1;
        g_iso[i] = rsqrtf((float)dout);
        g_isi[i] = rsqrtf((float)din);
    }
    int x = v;
    #pragma unroll
    for (int off = 1; off < 32; off <<= 1) {
        int y = __shfl_up_sync(0xffffffffu, x, off);
        if (lane >= off) x += y;
    }
    if (lane == 31) ws[w] = x;
    __syncthreads();
    if (t < 8) {
        int s = ws[t];
        int xs = s;
        #pragma unroll
        for (int off = 1; off < 8; off <<= 1) {
            int y = __shfl_up_sync(0xffu, xs, off);
            if (t >= off) xs += y;
        }
        ws[t] = xs - s;
    }
    __syncthreads();
    int excl = ws[w] + (x - v);
    if (i < N_NODES) g_rowptr[i] = excl;
    if (t == 255) g_bsum[blockIdx.x] = excl + v;
}

// fused mid-scan (redundant per block, 196 elems) + add
__global__ void k_scan_add() {
    __shared__ int ws[8];
    __shared__ int excl_s[256];
    int t = threadIdx.x, lane = t & 31, w = t >> 5;
    int v = (t < NBLK_SCAN) ? g_bsum[t] : 0;
    int x = v;
    #pragma unroll
    for (int off = 1; off < 32; off <<= 1) {
        int y = __shfl_up_sync(0xffffffffu, x, off);
        if (lane >= off) x += y;
    }
    if (lane == 31) ws[w] = x;
    __syncthreads();
    if (t < 8) {
        int s = ws[t];
        int xs = s;
        #pragma unroll
        for (int off = 1; off < 8; off <<= 1) {
            int y = __shfl_up_sync(0xffu, xs, off);
            if (t >= off) xs += y;
        }
        ws[t] = xs - s;
    }
    __syncthreads();
    excl_s[t] = ws[w] + (x - v);
    __syncthreads();
    int add = excl_s[blockIdx.x];
    int i = blockIdx.x * 256 + t;
    if (i < N_NODES) {
        int r = g_rowptr[i] + add;
        g_rowptr[i] = r;
        g_cursor[i] = r;
    }
    if (i == 0) g_rowptr[N_NODES] = N_EDGES;
}

__global__ void k_fill_csr(const int* __restrict__ src, const int* __restrict__ dst,
                           const float* __restrict__ ew) {
    int e = blockIdx.x * blockDim.x + threadIdx.x;
    if (e < N_EDGES) {
        int d = dst[e];
        int p = atomicAdd(&g_cursor[d], 1);
        g_epack[p] = make_int2(src[e], __float_as_int(ew[e]));
    }
}

// ---------------- bf16 split-3 tensor GEMM (single-buffer, 3 CTAs/SM) ----------------
// modes: 0 = fp32 A (no scale) -> fp32 Cf   (residual)
//        1 = fp32 A (*iso)     -> fp16 Ch   (layer 1)
//        2 = pre-split bf16 A  -> fp16 Ch   (layers 2-4)
// stage layout (bytes): A_hi[128][40]bf16 @0 (10240), A_lo @10240, W_hi[32][136] @20480 (8704), W_lo @29184
#define STG 37888
#define GEMM_SMEM (STG + 512)     // + ss[128]
__global__ void __launch_bounds__(256, 3) k_gemm_bf(
    const float* __restrict__ Af, const __nv_bfloat16* __restrict__ Axh,
    const __nv_bfloat16* __restrict__ Axl, const float* __restrict__ scale,
    const __nv_bfloat16* __restrict__ wh, const __nv_bfloat16* __restrict__ wl,
    float* __restrict__ Cf, __half* __restrict__ Ch, int mode) {
    extern __shared__ __align__(16) char pool[];
    float* ss = (float*)(pool + STG);
    const int tid  = threadIdx.x;
    const int warp = tid >> 5;
    const int lane = tid & 31;
    const int wm   = warp >> 1;          // 0..3 : 32-row slab
    const int wn   = warp & 1;           // 0..1 : 64-col slab
    const int row0 = blockIdx.x * BM;
    const int LDA = BK + 8;      // 40 bf16 = 80 B rows
    const int LDW = DIM + 8;     // 136 bf16 = 272 B rows
    const uint32_t poolS = (uint32_t)__cvta_generic_to_shared(pool);

    if (mode != 2 && tid < BM) {
        int gr = row0 + tid;
        ss[tid] = (gr < N_NODES) ? (mode ? scale[gr] : 1.0f) : 0.0f;
    }
    if (mode != 2) __syncthreads();   // ss visible

    // async copy of W tile for chunk k0 (32 rows x 256B, hi+lo)
    auto copyW = [&](int k0) {
        uint32_t base = poolS + 20480;
        #pragma unroll
        for (int u = tid; u < 512; u += 256) {         // 32 rows x 16 chunks of 16B
            int r = u >> 4, c16 = (u & 15) * 16;
            cp16(base + r * 272 + c16, (const char*)&wh[(k0 + r) * DIM] + c16);
            cp16(base + 8704 + r * 272 + c16, (const char*)&wl[(k0 + r) * DIM] + c16);
        }
    };
    // async copy of pre-split A tile (mode 2): 128 rows x 64B, hi+lo
    auto copyA2 = [&](int k0) {
        #pragma unroll
        for (int u = tid; u < 512; u += 256) {         // 128 rows x 4 chunks of 16B
            int r = u >> 2, c16 = (u & 3) * 16;
            const char* sh = (const char*)&Axh[(row0 + r) * DIM + k0] + c16;
            const char* sl = (const char*)&Axl[(row0 + r) * DIM + k0] + c16;
            cp16(poolS + r * 80 + c16, sh);
            cp16(poolS + 10240 + r * 80 + c16, sl);
        }
    };
    // synchronous A convert (modes 0/1)
    auto convA = [&](int k0) {
        __nv_bfloat16* As_hi = (__nv_bfloat16*)(pool);
        __nv_bfloat16* As_lo = (__nv_bfloat16*)(pool + 10240);
        #pragma unroll
        for (int u = tid; u < BM * (BK / 4); u += 256) {
            int r = u >> 3, q = (u & 7) * 4;
            int gr = row0 + r;
            float4 v = make_float4(0.f, 0.f, 0.f, 0.f);
            if (gr < N_NODES) v = *(const float4*)&Af[gr * DIM + k0 + q];
            float sc = ss[r];
            v.x *= sc; v.y *= sc; v.z *= sc; v.w *= sc;
            __nv_bfloat16 hx = __float2bfloat16(v.x);
            __nv_bfloat16 hy = __float2bfloat16(v.y);
            __nv_bfloat16 hz = __float2bfloat16(v.z);
            __nv_bfloat16 hw = __float2bfloat16(v.w);
            __nv_bfloat16* ph = &As_hi[r * LDA + q];
            __nv_bfloat16* pl = &As_lo[r * LDA + q];
            ph[0] = hx; ph[1] = hy; ph[2] = hz; ph[3] = hw;
            pl[0] = __float2bfloat16(v.x - __bfloat162float(hx));
            pl[1] = __float2bfloat16(v.y - __bfloat162float(hy));
            pl[2] = __float2bfloat16(v.z - __bfloat162float(hz));
            pl[3] = __float2bfloat16(v.w - __bfloat162float(hw));
        }
    };

    wmma::fragment<wmma::accumulator, 16, 16, 16, float> c[2][4];
    #pragma unroll
    for (int m = 0; m < 2; m++)
        #pragma unroll
        for (int n = 0; n < 4; n++) wmma::fill_fragment(c[m][n], 0.0f);

    const __nv_bfloat16* As_hi = (const __nv_bfloat16*)(pool);
    const __nv_bfloat16* As_lo = (const __nv_bfloat16*)(pool + 10240);
    const __nv_bfloat16* Ws_hi = (const __nv_bfloat16*)(pool + 20480);
    const __nv_bfloat16* Ws_lo = (const __nv_bfloat16*)(pool + 29184);

    for (int chunk = 0; chunk < DIM / BK; chunk++) {
        int k0 = chunk * BK;
        if (mode == 2) copyA2(k0);
        else           convA(k0);
        copyW(k0);
        CP_COMMIT();
        CP_WAIT0();
        __syncthreads();

        #pragma unroll
        for (int ks = 0; ks < BK / 16; ks++) {
            wmma::fragment<wmma::matrix_a, 16, 16, 16, __nv_bfloat16, wmma::row_major> ahi[2], alo[2];
            #pragma unroll
            for (int m = 0; m < 2; m++) {
                wmma::load_matrix_sync(ahi[m], &As_hi[(wm * 32 + m * 16) * LDA + ks * 16], LDA);
                wmma::load_matrix_sync(alo[m], &As_lo[(wm * 32 + m * 16) * LDA + ks * 16], LDA);
            }
            #pragma unroll
            for (int n = 0; n < 4; n++) {
                wmma::fragment<wmma::matrix_b, 16, 16, 16, __nv_bfloat16, wmma::row_major> bhi, blo;
                wmma::load_matrix_sync(bhi, &Ws_hi[(ks * 16) * LDW + wn * 64 + n * 16], LDW);
                wmma::load_matrix_sync(blo, &Ws_lo[(ks * 16) * LDW + wn * 64 + n * 16], LDW);
                #pragma unroll
                for (int m = 0; m < 2; m++) {
                    wmma::mma_sync(c[m][n], ahi[m], bhi, c[m][n]);
                    wmma::mma_sync(c[m][n], ahi[m], blo, c[m][n]);
                    wmma::mma_sync(c[m][n], alo[m], bhi, c[m][n]);
                }
            }
        }
        __syncthreads();   // smem free before next chunk overwrites
    }

    if (Ch) {
        // fp16 epilogue: per-warp-exclusive staging (16x64 fp32 per phase)
        float* stage = (float*)pool + warp * 16 * 64;
        #pragma unroll
        for (int m = 0; m < 2; m++) {
            #pragma unroll
            for (int n = 0; n < 4; n++)
                wmma::store_matrix_sync(&stage[n * 16], c[m][n], 64, wmma::mem_row_major);
            #pragma unroll
            for (int k = 0; k < 16; k++) {
                int idx = lane + k * 32;                // 0..511 half2 units
                int r = idx >> 5, h2c = (idx & 31) * 2;
                float f0 = stage[r * 64 + h2c];
                float f1 = stage[r * 64 + h2c + 1];
                int gr = row0 + wm * 32 + m * 16 + r;   // padded: no guard
                *(__half2*)&Ch[gr * DIM + wn * 64 + h2c] = __floats2half2_rn(f0, f1);
            }
        }
    } else {
        #pragma unroll
        for (int m = 0; m < 2; m++) {
            int gr0 = row0 + wm * 32 + m * 16;
            #pragma unroll
            for (int n = 0; n < 4; n++)
                wmma::store_matrix_sync(&Cf[gr0 * DIM + wn * 64 + n * 16], c[m][n], DIM, wmma::mem_row_major);
        }
    }
}

// ---------------- SpMM: one warp per dst row, fp16 gather, packed edges, MLP=8 ----------------
// omode 0: write bf16 hi/lo of (result * iso[row])  (feeds next GEMM)
// omode 1: write fp32 result (+res+br)              (feeds k_out)
__global__ void __launch_bounds__(256) k_spmm(
    const __half* __restrict__ h, const float* __restrict__ bias,
    const float* __restrict__ res, const float* __restrict__ bias2,
    __nv_bfloat16* __restrict__ outH, __nv_bfloat16* __restrict__ outL,
    float* __restrict__ outF, int omode) {
    int warp = (blockIdx.x * blockDim.x + threadIdx.x) >> 5;
    int lane = threadIdx.x & 31;
    if (warp >= N_NODES) return;
    int beg = g_rowptr[warp], end = g_rowptr[warp + 1];
    float4 acc = make_float4(0.f, 0.f, 0.f, 0.f);
    int e = beg;
    const int co = lane * 4;     // 4 half columns per lane = 8 bytes
    for (; e + 7 < end; e += 8) {
        int2 p[8]; uint2 u[8];
        #pragma unroll
        for (int j = 0; j < 8; j++) p[j] = g_epack[e + j];
        #pragma unroll
        for (int j = 0; j < 8; j++) u[j] = *(const uint2*)&h[p[j].x * DIM + co];
        #pragma unroll
        for (int j = 0; j < 8; j++) {
            float w = __int_as_float(p[j].y);
            float2 a = __half22float2(*(__half2*)&u[j].x);
            float2 b = __half22float2(*(__half2*)&u[j].y);
            acc.x += w * a.x; acc.y += w * a.y;
            acc.z += w * b.x; acc.w += w * b.y;
        }
    }
    for (; e < end; e++) {
        int2 p0 = g_epack[e];
        float w0 = __int_as_float(p0.y);
        uint2 u0 = *(const uint2*)&h[p0.x * DIM + co];
        float2 a0 = __half22float2(*(__half2*)&u0.x), b0 = __half22float2(*(__half2*)&u0.y);
        acc.x += w0 * a0.x; acc.y += w0 * a0.y;
        acc.z += w0 * b0.x; acc.w += w0 * b0.y;
    }
    float si = g_isi[warp];
    float4 b = *(const float4*)&bias[co];
    float4 o;
    o.x = acc.x * si + b.x; o.y = acc.y * si + b.y;
    o.z = acc.z * si + b.z; o.w = acc.w * si + b.w;
    if (omode == 1) {
        float4 r = *(const float4*)&res[warp * DIM + co];
        float4 b2 = *(const float4*)&bias2[co];
        o.x = fmaxf(o.x + r.x + b2.x, 0.f);
        o.y = fmaxf(o.y + r.y + b2.y, 0.f);
        o.z = fmaxf(o.z + r.z + b2.z, 0.f);
        o.w = fmaxf(o.w + r.w + b2.w, 0.f);
        *(float4*)&outF[warp * DIM + co] = o;
    } else {
        o.x = fmaxf(o.x, 0.f); o.y = fmaxf(o.y, 0.f);
        o.z = fmaxf(o.z, 0.f); o.w = fmaxf(o.w, 0.f);
        float so = g_iso[warp];         // fold next layer's out-degree scale
        o.x *= so; o.y *= so; o.z *= so; o.w *= so;
        __nv_bfloat16 hx = __float2bfloat16(o.x);
        __nv_bfloat16 hy = __float2bfloat16(o.y);
        __nv_bfloat16 hz = __float2bfloat16(o.z);
        __nv_bfloat16 hw = __float2bfloat16(o.w);
        __nv_bfloat16 h4[4] = {hx, hy, hz, hw};
        __nv_bfloat16 l4[4] = {
            __float2bfloat16(o.x - __bfloat162float(hx)),
            __float2bfloat16(o.y - __bfloat162float(hy)),
            __float2bfloat16(o.z - __bfloat162float(hz)),
            __float2bfloat16(o.w - __bfloat162float(hw))};
        *(uint2*)&outH[warp * DIM + co] = *(uint2*)h4;
        *(uint2*)&outL[warp * DIM + co] = *(uint2*)l4;
    }
}

// ---------------- output head: out[N,16] = z[N,128] @ Wo[128,16] + bo ----------------
__global__ void __launch_bounds__(256) k_out(
    const float* __restrict__ z, const float* __restrict__ Wo,
    const float* __restrict__ bo, float* __restrict__ out) {
    __shared__ float sz[64][132];
    __shared__ float sw[DIM][NCLS];
    int r0 = blockIdx.x * 64;
    for (int i = threadIdx.x; i < DIM * NCLS; i += 256)
        sw[i >> 4][i & 15] = Wo[i];
    for (int i = threadIdx.x; i < 2048; i += 256) {
        int row = i >> 5, c4 = (i & 31) * 4;
        int gr = r0 + row;
        float4 v = (gr < N_NODES) ? *(const float4*)&z[gr * DIM + c4]
                                  : make_float4(0.f, 0.f, 0.f, 0.f);
        *(float4*)&sz[row][c4] = v;
    }
    __syncthreads();
    int row = threadIdx.x >> 2;
    int cg  = (threadIdx.x & 3) * 4;
    float a0 = 0.f, a1 = 0.f, a2 = 0.f, a3 = 0.f;
    #pragma unroll 8
    for (int k = 0; k < DIM; k++) {
        float zv = sz[row][k];
        a0 += zv * sw[k][cg];     a1 += zv * sw[k][cg + 1];
        a2 += zv * sw[k][cg + 2]; a3 += zv * sw[k][cg + 3];
    }
    int gr = r0 + row;
    if (gr < N_NODES) {
        out[gr * NCLS + cg]     = a0 + bo[cg];
        out[gr * NCLS + cg + 1] = a1 + bo[cg + 1];
        out[gr * NCLS + cg + 2] = a2 + bo[cg + 2];
        out[gr * NCLS + cg + 3] = a3 + bo[cg + 3];
    }
}

// ---------------- launch ----------------
extern "C" void kernel_launch(void* const* d_in, const int* in_sizes, int n_in,
                              void* d_out, int out_size) {
    const int*   src = (const int*)d_in[0];
    const int*   dst = (const int*)d_in[1];
    const float* xin = (const float*)d_in[2];
    const float* ew  = (const float*)d_in[3];
    const float* W1 = (const float*)d_in[4];  const float* b1 = (const float*)d_in[5];
    const float* W2 = (const float*)d_in[6];  const float* b2 = (const float*)d_in[7];
    const float* W3 = (const float*)d_in[8];  const float* b3 = (const float*)d_in[9];
    const float* W4 = (const float*)d_in[10]; const float* b4 = (const float*)d_in[11];
    const float* Wr = (const float*)d_in[12]; const float* br = (const float*)d_in[13];
    const float* Wo = (const float*)d_in[14]; const float* bo = (const float*)d_in[15];
    float* out = (float*)d_out;

    float *p_x, *p_res, *p_iso;
    __half *p_h16;
    __nv_bfloat16 *p_wh, *p_wl, *p_xh, *p_xl;
    cudaGetSymbolAddress((void**)&p_h16, g_h16);
    cudaGetSymbolAddress((void**)&p_x,   g_x);
    cudaGetSymbolAddress((void**)&p_res, g_res);
    cudaGetSymbolAddress((void**)&p_iso, g_iso);
    cudaGetSymbolAddress((void**)&p_wh,  g_wbh);
    cudaGetSymbolAddress((void**)&p_wl,  g_wbl);
    cudaGetSymbolAddress((void**)&p_xh,  g_xh);
    cudaGetSymbolAddress((void**)&p_xl,  g_xl);

    cudaFuncSetAttribute(k_gemm_bf, cudaFuncAttributeMaxDynamicSharedMemorySize, GEMM_SMEM);

    const int TB = 256;
    int nB_edges = (N_EDGES + TB - 1) / TB;                 // 3125
    int nB_out   = (N_NODES + 63) / 64;                     // 782
    int nB_spmm  = (N_NODES + (TB / 32) - 1) / (TB / 32);   // 6250

    // graph preprocessing (shared by all 4 layers)
    k_init<<<NBLK_SCAN, TB>>>(W1, W2, W3, W4, Wr);
    k_degrees<<<nB_edges, TB>>>(src, dst);
    k_scan_part<<<NBLK_SCAN, TB>>>();
    k_scan_add<<<NBLK_SCAN, TB>>>();
    k_fill_csr<<<nB_edges, TB>>>(src, dst, ew);

    // residual branch: fp32 output (br folded into layer-4 SpMM epilogue)
    k_gemm_bf<<<NB_GEMM, TB, GEMM_SMEM>>>(xin, nullptr, nullptr, nullptr,
                               p_wh + 4 * DIM * DIM, p_wl + 4 * DIM * DIM, p_res, nullptr, 0);

    // layer 1 (fp32 input, iso in-GEMM)
    k_gemm_bf<<<NB_GEMM, TB, GEMM_SMEM>>>(xin, nullptr, nullptr, p_iso,
                               p_wh + 0 * DIM * DIM, p_wl + 0 * DIM * DIM, nullptr, p_h16, 1);
    k_spmm<<<nB_spmm, TB>>>(p_h16, b1, nullptr, nullptr, p_xh, p_xl, nullptr, 0);
    // layer 2 (pre-split input, iso pre-folded)
    k_gemm_bf<<<NB_GEMM, TB, GEMM_SMEM>>>(nullptr, p_xh, p_xl, nullptr,
                               p_wh + 1 * DIM * DIM, p_wl + 1 * DIM * DIM, nullptr, p_h16, 2);
    k_spmm<<<nB_spmm, TB>>>(p_h16, b2, nullptr, nullptr, p_xh, p_xl, nullptr, 0);
    // layer 3
    k_gemm_bf<<<NB_GEMM, TB, GEMM_SMEM>>>(nullptr, p_xh, p_xl, nullptr,
                               p_wh + 2 * DIM * DIM, p_wl + 2 * DIM * DIM, nullptr, p_h16, 2);
    k_spmm<<<nB_spmm, TB>>>(p_h16, b3, nullptr, nullptr, p_xh, p_xl, nullptr, 0);
    // layer 4 + residual (+br) + relu -> fp32 x
    k_gemm_bf<<<NB_GEMM, TB, GEMM_SMEM>>>(nullptr, p_xh, p_xl, nullptr,
                               p_wh + 3 * DIM * DIM, p_wl + 3 * DIM * DIM, nullptr, p_h16, 2);
    k_spmm<<<nB_spmm, TB>>>(p_h16, b4, p_res, br, nullptr, nullptr, p_x, 1);

    // output head
    k_out<<<nB_out, TB>>>(p_x, Wo, bo, out);
}

// round 17
// speedup vs baseline: 1.2379x; 1.2379x over previous
#include <cuda_runtime.h>
#include <cuda_bf16.h>
#include <cuda_fp16.h>
#include <mma.h>
#include <cstdint>

using namespace nvcuda;

#define N_NODES 50000
#define N_EDGES 800000
#define DIM 128
#define NCLS 16
#define BM 128
#define BK 32
#define N_PAD 50048            // 391 * 128, padded scratch rows
#define NBLK_SCAN 196          // ceil(50000/256)
#define NB_GEMM 391

// ---------------- scratch (allocation-free: __device__ globals) ----------------
__device__ __half g_h16[N_PAD * DIM];          // post-GEMM features, fp16 (SpMM gather)
__device__ __nv_bfloat16 g_xh[N_PAD * DIM];    // pre-split (x*iso) hi  (GEMM A input)
__device__ __nv_bfloat16 g_xl[N_PAD * DIM];    // pre-split (x*iso) lo
__device__ float g_x[N_PAD * DIM];             // final activations, fp32 (k_out input)
__device__ float g_res[N_PAD * DIM];           // residual branch, fp32
__device__ float g_iso[N_NODES];
__device__ float g_isi[N_NODES];
__device__ int   g_dego[N_NODES];
__device__ int   g_degi[N_NODES];
__device__ int   g_rowptr[N_NODES + 1];
__device__ int   g_cursor[N_NODES];
__device__ int   g_bsum[NBLK_SCAN];
__device__ int2  g_epack[N_EDGES];             // (src, weight bits)
__device__ __nv_bfloat16 g_wbh[5 * DIM * DIM]; // bf16 hi of weights, natural [k][n]
__device__ __nv_bfloat16 g_wbl[5 * DIM * DIM]; // bf16 lo residuals

// ---------------- cp.async helpers ----------------
__device__ __forceinline__ void cp16(uint32_t dst, const void* src) {
    asm volatile("cp.async.cg.shared.global [%0], [%1], 16;" :: "r"(dst), "l"(src));
}
#define CP_COMMIT() asm volatile("cp.async.commit_group;" ::: "memory")
#define CP_WAIT1()  asm volatile("cp.async.wait_group 1;" ::: "memory")
#define CP_WAIT0()  asm volatile("cp.async.wait_group 0;" ::: "memory")

// ---------------- graph preprocessing ----------------
// fused: zero degrees + split all 5 weights into bf16 hi/lo
__global__ void k_init(const float* __restrict__ W1, const float* __restrict__ W2,
                       const float* __restrict__ W3, const float* __restrict__ W4,
                       const float* __restrict__ Wr) {
    const float* Ws[5] = {W1, W2, W3, W4, Wr};
    int i = blockIdx.x * 256 + threadIdx.x;      // 0..50175
    if (i < N_NODES) { g_dego[i] = 0; g_degi[i] = 0; }
    for (int j = i; j < 5 * DIM * DIM; j += NBLK_SCAN * 256) {
        int w = j >> 14;                          // /16384
        int k = j & (DIM * DIM - 1);
        float v = Ws[w][k];
        __nv_bfloat16 hi = __float2bfloat16(v);
        g_wbh[j] = hi;
        g_wbl[j] = __float2bfloat16(v - __bfloat162float(hi));
    }
}

__global__ void k_degrees(const int* __restrict__ src, const int* __restrict__ dst) {
    int e = blockIdx.x * blockDim.x + threadIdx.x;
    if (e < N_EDGES) {
        atomicAdd(&g_dego[src[e]], 1);
        atomicAdd(&g_degi[dst[e]], 1);
    }
}

// block-level scan of degi + invsqrt of both degrees (fused)
__global__ void k_scan_part() {
    __shared__ int ws[8];
    int t = threadIdx.x, lane = t & 31, w = t >> 5;
    int i = blockIdx.x * 256 + t;
    int v = (i < N_NODES) ? g_degi[i] : 0;
    if (i < N_NODES) {
        int dout = g_dego[i]; if (dout < 1) dout = 1;
        int din  = v;         if (din  < 1) din  = 1;
        g_iso[i] = rsqrtf((float)dout);
        g_isi[i] = rsqrtf((float)din);
    }
    int x = v;
    #pragma unroll
    for (int off = 1; off < 32; off <<= 1) {
        int y = __shfl_up_sync(0xffffffffu, x, off);
        if (lane >= off) x += y;
    }
    if (lane == 31) ws[w] = x;
    __syncthreads();
    if (t < 8) {
        int s = ws[t];
        int xs = s;
        #pragma unroll
        for (int off = 1; off < 8; off <<= 1) {
            int y = __shfl_up_sync(0xffu, xs, off);
            if (t >= off) xs += y;
        }
        ws[t] = xs - s;
    }
    __syncthreads();
    int excl = ws[w] + (x - v);
    if (i < N_NODES) g_rowptr[i] = excl;
    if (t == 255) g_bsum[blockIdx.x] = excl + v;
}

// fused mid-scan (redundant per block, 196 elems) + add
__global__ void k_scan_add() {
    __shared__ int ws[8];
    __shared__ int excl_s[256];
    int t = threadIdx.x, lane = t & 31, w = t >> 5;
    int v = (t < NBLK_SCAN) ? g_bsum[t] : 0;
    int x = v;
    #pragma unroll
    for (int off = 1; off < 32; off <<= 1) {
        int y = __shfl_up_sync(0xffffffffu, x, off);
        if (lane >= off) x += y;
    }
    if (lane == 31) ws[w] = x;
    __syncthreads();
    if (t < 8) {
        int s = ws[t];
        int xs = s;
        #pragma unroll
        for (int off = 1; off < 8; off <<= 1) {
            int y = __shfl_up_sync(0xffu, xs, off);
            if (t >= off) xs += y;
        }
        ws[t] = xs - s;
    }
    __syncthreads();
    excl_s[t] = ws[w] + (x - v);
    __syncthreads();
    int add = excl_s[blockIdx.x];
    int i = blockIdx.x * 256 + t;
    if (i < N_NODES) {
        int r = g_rowptr[i] + add;
        g_rowptr[i] = r;
        g_cursor[i] = r;
    }
    if (i == 0) g_rowptr[N_NODES] = N_EDGES;
}

__global__ void k_fill_csr(const int* __restrict__ src, const int* __restrict__ dst,
                           const float* __restrict__ ew) {
    int e = blockIdx.x * blockDim.x + threadIdx.x;
    if (e < N_EDGES) {
        int d = dst[e];
        int p = atomicAdd(&g_cursor[d], 1);
        g_epack[p] = make_int2(src[e], __float_as_int(ew[e]));
    }
}

// ---------------- bf16 split-3 tensor GEMM (cp.async double-buffered, 2 CTAs/SM) ----------------
// modes: 0 = fp32 A (no scale) -> fp32 Cf   (residual)
//        1 = fp32 A (*iso)     -> fp16 Ch   (layer 1)
//        2 = pre-split bf16 A  -> fp16 Ch   (layers 2-4)
// stage layout (bytes): A_hi[128][40]bf16 @0 (10240), A_lo @10240, W_hi[32][136] @20480 (8704), W_lo @29184
#define STG 37888
#define GEMM_SMEM (2 * STG + 512)     // + ss[128]
__global__ void __launch_bounds__(256, 2) k_gemm_bf(
    const float* __restrict__ Af, const __nv_bfloat16* __restrict__ Axh,
    const __nv_bfloat16* __restrict__ Axl, const float* __restrict__ scale,
    const __nv_bfloat16* __restrict__ wh, const __nv_bfloat16* __restrict__ wl,
    float* __restrict__ Cf, __half* __restrict__ Ch, int mode) {
    extern __shared__ __align__(16) char pool[];
    float* ss = (float*)(pool + 2 * STG);
    const int tid  = threadIdx.x;
    const int warp = tid >> 5;
    const int lane = tid & 31;
    const int wm   = warp >> 1;          // 0..3 : 32-row slab
    const int wn   = warp & 1;           // 0..1 : 64-col slab
    const int row0 = blockIdx.x * BM;
    const int LDA = BK + 8;      // 40 bf16 = 80 B rows
    const int LDW = DIM + 8;     // 136 bf16 = 272 B rows
    const uint32_t poolS = (uint32_t)__cvta_generic_to_shared(pool);

    if (mode != 2 && tid < BM) {
        int gr = row0 + tid;
        ss[tid] = (gr < N_NODES) ? (mode ? scale[gr] : 1.0f) : 0.0f;
    }

    // async copy of W tile for chunk k0 into stage s (32 rows x 256B, hi+lo)
    auto copyW = [&](int s, int k0) {
        uint32_t base = poolS + s * STG + 20480;
        #pragma unroll
        for (int u = tid; u < 512; u += 256) {         // 32 rows x 16 chunks of 16B
            int r = u >> 4, c16 = (u & 15) * 16;
            cp16(base + r * 272 + c16, (const char*)&wh[(k0 + r) * DIM] + c16);
            cp16(base + 8704 + r * 272 + c16, (const char*)&wl[(k0 + r) * DIM] + c16);
        }
    };
    // async copy of pre-split A tile (mode 2): 128 rows x 64B, hi+lo
    auto copyA2 = [&](int s, int k0) {
        uint32_t base = poolS + s * STG;
        #pragma unroll
        for (int u = tid; u < 512; u += 256) {         // 128 rows x 4 chunks of 16B
            int r = u >> 2, c16 = (u & 3) * 16;
            const char* sh = (const char*)&Axh[(row0 + r) * DIM + k0] + c16;
            const char* sl = (const char*)&Axl[(row0 + r) * DIM + k0] + c16;
            cp16(base + r * 80 + c16, sh);
            cp16(base + 10240 + r * 80 + c16, sl);
        }
    };
    // synchronous A convert (modes 0/1)
    auto convA = [&](int s, int k0) {
        __nv_bfloat16* As_hi = (__nv_bfloat16*)(pool + s * STG);
        __nv_bfloat16* As_lo = (__nv_bfloat16*)(pool + s * STG + 10240);
        #pragma unroll
        for (int u = tid; u < BM * (BK / 4); u += 256) {
            int r = u >> 3, q = (u & 7) * 4;
            int gr = row0 + r;
            float4 v = make_float4(0.f, 0.f, 0.f, 0.f);
            if (gr < N_NODES) v = *(const float4*)&Af[gr * DIM + k0 + q];
            float sc = ss[r];
            v.x *= sc; v.y *= sc; v.z *= sc; v.w *= sc;
            __nv_bfloat16 hx = __float2bfloat16(v.x);
            __nv_bfloat16 hy = __float2bfloat16(v.y);
            __nv_bfloat16 hz = __float2bfloat16(v.z);
            __nv_bfloat16 hw = __float2bfloat16(v.w);
            __nv_bfloat16* ph = &As_hi[r * LDA + q];
            __nv_bfloat16* pl = &As_lo[r * LDA + q];
            ph[0] = hx; ph[1] = hy; ph[2] = hz; ph[3] = hw;
            pl[0] = __float2bfloat16(v.x - __bfloat162float(hx));
            pl[1] = __float2bfloat16(v.y - __bfloat162float(hy));
            pl[2] = __float2bfloat16(v.z - __bfloat162float(hz));
            pl[3] = __float2bfloat16(v.w - __bfloat162float(hw));
        }
    };

    wmma::fragment<wmma::accumulator, 16, 16, 16, float> c[2][4];
    #pragma unroll
    for (int m = 0; m < 2; m++)
        #pragma unroll
        for (int n = 0; n < 4; n++) wmma::fill_fragment(c[m][n], 0.0f);

    // prologue: issue chunk 0
    if (mode == 2) copyA2(0, 0);
    copyW(0, 0);
    CP_COMMIT();
    if (mode != 2) {
        __syncthreads();   // ss visible before convA
        convA(0, 0);
    }

    for (int chunk = 0; chunk < DIM / BK; chunk++) {
        int s = chunk & 1;
        if (chunk + 1 < DIM / BK) {
            int k1 = (chunk + 1) * BK;
            if (mode == 2) copyA2(1 - s, k1);
            copyW(1 - s, k1);
            CP_COMMIT();
            CP_WAIT1();
        } else {
            CP_WAIT0();
        }
        __syncthreads();

        const char* st = pool + s * STG;
        const __nv_bfloat16* As_hi = (const __nv_bfloat16*)(st);
        const __nv_bfloat16* As_lo = (const __nv_bfloat16*)(st + 10240);
        const __nv_bfloat16* Ws_hi = (const __nv_bfloat16*)(st + 20480);
        const __nv_bfloat16* Ws_lo = (const __nv_bfloat16*)(st + 29184);
        #pragma unroll
        for (int ks = 0; ks < BK / 16; ks++) {
            wmma::fragment<wmma::matrix_a, 16, 16, 16, __nv_bfloat16, wmma::row_major> ahi[2], alo[2];
            #pragma unroll
            for (int m = 0; m < 2; m++) {
                wmma::load_matrix_sync(ahi[m], &As_hi[(wm * 32 + m * 16) * LDA + ks * 16], LDA);
                wmma::load_matrix_sync(alo[m], &As_lo[(wm * 32 + m * 16) * LDA + ks * 16], LDA);
            }
            #pragma unroll
            for (int n = 0; n < 4; n++) {
                wmma::fragment<wmma::matrix_b, 16, 16, 16, __nv_bfloat16, wmma::row_major> bhi, blo;
                wmma::load_matrix_sync(bhi, &Ws_hi[(ks * 16) * LDW + wn * 64 + n * 16], LDW);
                wmma::load_matrix_sync(blo, &Ws_lo[(ks * 16) * LDW + wn * 64 + n * 16], LDW);
                #pragma unroll
                for (int m = 0; m < 2; m++) {
                    wmma::mma_sync(c[m][n], ahi[m], bhi, c[m][n]);
                    wmma::mma_sync(c[m][n], ahi[m], blo, c[m][n]);
                    wmma::mma_sync(c[m][n], alo[m], bhi, c[m][n]);
                }
            }
        }
        __syncthreads();
        // convert A for the next chunk (modes 0/1) into the buffer just freed
        if (mode != 2 && chunk + 1 < DIM / BK)
            convA(1 - s, (chunk + 1) * BK);
    }

    if (Ch) {
        // fp16 epilogue: per-warp-exclusive staging (16x64 fp32 per phase)
        float* stage = (float*)pool + warp * 16 * 64;
        #pragma unroll
        for (int m = 0; m < 2; m++) {
            #pragma unroll
            for (int n = 0; n < 4; n++)
                wmma::store_matrix_sync(&stage[n * 16], c[m][n], 64, wmma::mem_row_major);
            #pragma unroll
            for (int k = 0; k < 16; k++) {
                int idx = lane + k * 32;                // 0..511 half2 units
                int r = idx >> 5, h2c = (idx & 31) * 2;
                float f0 = stage[r * 64 + h2c];
                float f1 = stage[r * 64 + h2c + 1];
                int gr = row0 + wm * 32 + m * 16 + r;   // padded: no guard
                *(__half2*)&Ch[gr * DIM + wn * 64 + h2c] = __floats2half2_rn(f0, f1);
            }
        }
    } else {
        #pragma unroll
        for (int m = 0; m < 2; m++) {
            int gr0 = row0 + wm * 32 + m * 16;
            #pragma unroll
            for (int n = 0; n < 4; n++)
                wmma::store_matrix_sync(&Cf[gr0 * DIM + wn * 64 + n * 16], c[m][n], DIM, wmma::mem_row_major);
        }
    }
}

// ---------------- SpMM: one warp per dst row, fp16 gather, packed edges, MLP=8 ----------------
// omode 0: write bf16 hi/lo of (result * iso[row])  (feeds next GEMM)
// omode 1: write fp32 result (+res+br)              (feeds k_out)
__global__ void __launch_bounds__(256) k_spmm(
    const __half* __restrict__ h, const float* __restrict__ bias,
    const float* __restrict__ res, const float* __restrict__ bias2,
    __nv_bfloat16* __restrict__ outH, __nv_bfloat16* __restrict__ outL,
    float* __restrict__ outF, int omode) {
    int warp = (blockIdx.x * blockDim.x + threadIdx.x) >> 5;
    int lane = threadIdx.x & 31;
    if (warp >= N_NODES) return;
    int beg = g_rowptr[warp], end = g_rowptr[warp + 1];
    float4 acc = make_float4(0.f, 0.f, 0.f, 0.f);
    int e = beg;
    const int co = lane * 4;     // 4 half columns per lane = 8 bytes
    for (; e + 7 < end; e += 8) {
        int2 p[8]; uint2 u[8];
        #pragma unroll
        for (int j = 0; j < 8; j++) p[j] = g_epack[e + j];
        #pragma unroll
        for (int j = 0; j < 8; j++) u[j] = *(const uint2*)&h[p[j].x * DIM + co];
        #pragma unroll
        for (int j = 0; j < 8; j++) {
            float w = __int_as_float(p[j].y);
            float2 a = __half22float2(*(__half2*)&u[j].x);
            float2 b = __half22float2(*(__half2*)&u[j].y);
            acc.x += w * a.x; acc.y += w * a.y;
            acc.z += w * b.x; acc.w += w * b.y;
        }
    }
    for (; e < end; e++) {
        int2 p0 = g_epack[e];
        float w0 = __int_as_float(p0.y);
        uint2 u0 = *(const uint2*)&h[p0.x * DIM + co];
        float2 a0 = __half22float2(*(__half2*)&u0.x), b0 = __half22float2(*(__half2*)&u0.y);
        acc.x += w0 * a0.x; acc.y += w0 * a0.y;
        acc.z += w0 * b0.x; acc.w += w0 * b0.y;
    }
    float si = g_isi[warp];
    float4 b = *(const float4*)&bias[co];
    float4 o;
    o.x = acc.x * si + b.x; o.y = acc.y * si + b.y;
    o.z = acc.z * si + b.z; o.w = acc.w * si + b.w;
    if (omode == 1) {
        float4 r = *(const float4*)&res[warp * DIM + co];
        float4 b2 = *(const float4*)&bias2[co];
        o.x = fmaxf(o.x + r.x + b2.x, 0.f);
        o.y = fmaxf(o.y + r.y + b2.y, 0.f);
        o.z = fmaxf(o.z + r.z + b2.z, 0.f);
        o.w = fmaxf(o.w + r.w + b2.w, 0.f);
        *(float4*)&outF[warp * DIM + co] = o;
    } else {
        o.x = fmaxf(o.x, 0.f); o.y = fmaxf(o.y, 0.f);
        o.z = fmaxf(o.z, 0.f); o.w = fmaxf(o.w, 0.f);
        float so = g_iso[warp];         // fold next layer's out-degree scale
        o.x *= so; o.y *= so; o.z *= so; o.w *= so;
        __nv_bfloat16 hx = __float2bfloat16(o.x);
        __nv_bfloat16 hy = __float2bfloat16(o.y);
        __nv_bfloat16 hz = __float2bfloat16(o.z);
        __nv_bfloat16 hw = __float2bfloat16(o.w);
        __nv_bfloat16 h4[4] = {hx, hy, hz, hw};
        __nv_bfloat16 l4[4] = {
            __float2bfloat16(o.x - __bfloat162float(hx)),
            __float2bfloat16(o.y - __bfloat162float(hy)),
            __float2bfloat16(o.z - __bfloat162float(hz)),
            __float2bfloat16(o.w - __bfloat162float(hw))};
        *(uint2*)&outH[warp * DIM + co] = *(uint2*)h4;
        *(uint2*)&outL[warp * DIM + co] = *(uint2*)l4;
    }
}

// ---------------- output head: out[N,16] = z[N,128] @ Wo[128,16] + bo ----------------
__global__ void __launch_bounds__(256) k_out(
    const float* __restrict__ z, const float* __restrict__ Wo,
    const float* __restrict__ bo, float* __restrict__ out) {
    __shared__ float sz[64][132];
    __shared__ float sw[DIM][NCLS];
    int r0 = blockIdx.x * 64;
    for (int i = threadIdx.x; i < DIM * NCLS; i += 256)
        sw[i >> 4][i & 15] = Wo[i];
    for (int i = threadIdx.x; i < 2048; i += 256) {
        int row = i >> 5, c4 = (i & 31) * 4;
        int gr = r0 + row;
        float4 v = (gr < N_NODES) ? *(const float4*)&z[gr * DIM + c4]
                                  : make_float4(0.f, 0.f, 0.f, 0.f);
        *(float4*)&sz[row][c4] = v;
    }
    __syncthreads();
    int row = threadIdx.x >> 2;
    int cg  = (threadIdx.x & 3) * 4;
    float a0 = 0.f, a1 = 0.f, a2 = 0.f, a3 = 0.f;
    #pragma unroll 8
    for (int k = 0; k < DIM; k++) {
        float zv = sz[row][k];
        a0 += zv * sw[k][cg];     a1 += zv * sw[k][cg + 1];
        a2 += zv * sw[k][cg + 2]; a3 += zv * sw[k][cg + 3];
    }
    int gr = r0 + row;
    if (gr < N_NODES) {
        out[gr * NCLS + cg]     = a0 + bo[cg];
        out[gr * NCLS + cg + 1] = a1 + bo[cg + 1];
        out[gr * NCLS + cg + 2] = a2 + bo[cg + 2];
        out[gr * NCLS + cg + 3] = a3 + bo[cg + 3];
    }
}

// ---------------- launch ----------------
extern "C" void kernel_launch(void* const* d_in, const int* in_sizes, int n_in,
                              void* d_out, int out_size) {
    const int*   src = (const int*)d_in[0];
    const int*   dst = (const int*)d_in[1];
    const float* xin = (const float*)d_in[2];
    const float* ew  = (const float*)d_in[3];
    const float* W1 = (const float*)d_in[4];  const float* b1 = (const float*)d_in[5];
    const float* W2 = (const float*)d_in[6];  const float* b2 = (const float*)d_in[7];
    const float* W3 = (const float*)d_in[8];  const float* b3 = (const float*)d_in[9];
    const float* W4 = (const float*)d_in[10]; const float* b4 = (const float*)d_in[11];
    const float* Wr = (const float*)d_in[12]; const float* br = (const float*)d_in[13];
    const float* Wo = (const float*)d_in[14]; const float* bo = (const float*)d_in[15];
    float* out = (float*)d_out;

    float *p_x, *p_res, *p_iso;
    __half *p_h16;
    __nv_bfloat16 *p_wh, *p_wl, *p_xh, *p_xl;
    cudaGetSymbolAddress((void**)&p_h16, g_h16);
    cudaGetSymbolAddress((void**)&p_x,   g_x);
    cudaGetSymbolAddress((void**)&p_res, g_res);
    cudaGetSymbolAddress((void**)&p_iso, g_iso);
    cudaGetSymbolAddress((void**)&p_wh,  g_wbh);
    cudaGetSymbolAddress((void**)&p_wl,  g_wbl);
    cudaGetSymbolAddress((void**)&p_xh,  g_xh);
    cudaGetSymbolAddress((void**)&p_xl,  g_xl);

    cudaFuncSetAttribute(k_gemm_bf, cudaFuncAttributeMaxDynamicSharedMemorySize, GEMM_SMEM);

    const int TB = 256;
    int nB_edges = (N_EDGES + TB - 1) / TB;                 // 3125
    int nB_out   = (N_NODES + 63) / 64;                     // 782
    int nB_spmm  = (N_NODES + (TB / 32) - 1) / (TB / 32);   // 6250

    // graph preprocessing (shared by all 4 layers)
    k_init<<<NBLK_SCAN, TB>>>(W1, W2, W3, W4, Wr);
    k_degrees<<<nB_edges, TB>>>(src, dst);
    k_scan_part<<<NBLK_SCAN, TB>>>();
    k_scan_add<<<NBLK_SCAN, TB>>>();
    k_fill_csr<<<nB_edges, TB>>>(src, dst, ew);

    // residual branch: fp32 output (br folded into layer-4 SpMM epilogue)
    k_gemm_bf<<<NB_GEMM, TB, GEMM_SMEM>>>(xin, nullptr, nullptr, nullptr,
                               p_wh + 4 * DIM * DIM, p_wl + 4 * DIM * DIM, p_res, nullptr, 0);

    // layer 1 (fp32 input, iso in-GEMM)
    k_gemm_bf<<<NB_GEMM, TB, GEMM_SMEM>>>(xin, nullptr, nullptr, p_iso,
                               p_wh + 0 * DIM * DIM, p_wl + 0 * DIM * DIM, nullptr, p_h16, 1);
    k_spmm<<<nB_spmm, TB>>>(p_h16, b1, nullptr, nullptr, p_xh, p_xl, nullptr, 0);
    // layer 2 (pre-split input, iso pre-folded)
    k_gemm_bf<<<NB_GEMM, TB, GEMM_SMEM>>>(nullptr, p_xh, p_xl, nullptr,
                               p_wh + 1 * DIM * DIM, p_wl + 1 * DIM * DIM, nullptr, p_h16, 2);
    k_spmm<<<nB_spmm, TB>>>(p_h16, b2, nullptr, nullptr, p_xh, p_xl, nullptr, 0);
    // layer 3
    k_gemm_bf<<<NB_GEMM, TB, GEMM_SMEM>>>(nullptr, p_xh, p_xl, nullptr,
                               p_wh + 2 * DIM * DIM, p_wl + 2 * DIM * DIM, nullptr, p_h16, 2);
    k_spmm<<<nB_spmm, TB>>>(p_h16, b3, nullptr, nullptr, p_xh, p_xl, nullptr, 0);
    // layer 4 + residual (+br) + relu -> fp32 x
    k_gemm_bf<<<NB_GEMM, TB, GEMM_SMEM>>>(nullptr, p_xh, p_xl, nullptr,
                               p_wh + 3 * DIM * DIM, p_wl + 3 * DIM * DIM, nullptr, p_h16, 2);
    k_spmm<<<nB_spmm, TB>>>(p_h16, b4, p_res, br, nullptr, nullptr, p_x, 1);

    // output head
    k_out<<<nB_out, TB>>>(p_x, Wo, bo, out);
}